// round 13
// baseline (speedup 1.0000x reference)
#include <cuda_runtime.h>
#include <cuda_bf16.h>
#include <math.h>

#define NN 131072
#define EE 2097152
#define DD 64
#define LL 3
#define RR 3
#define NBASE 2
#define BB 4096

// ---------------- device scratch (no allocs; zero-initialized at load) ----------------
// W layout: [conv][col][96 words]; word w: chunk=w>>5, t=w&31, ks=t>>3, q=(t>>1)&3, u=t&1
//   -> k-pair (local in chunk) = ks*8 + q + 4u  (pairs two MMA b-frag words adjacently)
__device__ unsigned g_WkH[6 * 64 * 96];     // bf16x2 hi pairs
__device__ unsigned g_WkL[6 * 64 * 96];     // bf16x2 lo pairs
__device__ float g_Bpack[6 * DD];
__device__ float g_AGGB[(size_t)NN * 128];  // 2 basis accumulators (compacted rows when IDX)
__device__ float g_Hl[(size_t)NN * DD];
__device__ float g_Hg0[(size_t)NN * DD];
__device__ float g_Hg1[(size_t)NN * DD];
__device__ float g_Hg2[(size_t)NN * DD];
// CSR + frontier structures (graph identical for all 6 convs)
__device__ int    g_cnt[NN];    // zeroed by k4 each call (zero-init on load)
__device__ int    g_flag[NN];   // zeroed by k4 each call
__device__ int    g_cur[NN];
__device__ int    g_rowptr[NN + 1];
__device__ float2 g_ep1[EE];    // (.x = bits(src*64+etype), .y = mask)  in CSR order
__device__ float2 g_ep2[EE];    // (.x = bits(src*64+etype), .y = mask2) in CSR order
__device__ int    g_blksum[512];
__device__ int    g_blkpre[512];
__device__ int    g_fsum[512];
__device__ int    g_fpre[512];
__device__ int    g_list[NN];
__device__ int    g_nfront;

// ---------------- packed f32x2 helpers ----------------
__device__ __forceinline__ unsigned long long pack2(float a, float b) {
    unsigned long long r;
    asm("mov.b64 %0, {%1, %2};" : "=l"(r) : "f"(a), "f"(b));
    return r;
}
#define FMA2(acc, w, h) \
    asm("fma.rn.f32x2 %0, %1, %2, %0;" : "+l"(acc) : "l"(w), "l"(h))

// ---------------- K1: count (CSR histogram) + frontier mark + weight prep (bf16 split) ----
#define COUNT_BLOCKS (EE / 256)          // 8192
#define PREP_ITEMS   (6 * 64 * 96)       // 36864
#define PREP_BLOCKS  ((PREP_ITEMS + 255) / 256)

__global__ void k1_combo(const int* __restrict__ src, const int* __restrict__ dst,
                         const float* __restrict__ lV, const float* __restrict__ lW,
                         const float* __restrict__ lB,
                         const float* __restrict__ gV, const float* __restrict__ gW,
                         const float* __restrict__ gB) {
    int b = blockIdx.x;
    if (b < COUNT_BLOCKS) {
        int e = b * 256 + threadIdx.x;
        int d = dst[e];
        atomicAdd(&g_cnt[d], 1);
        if (e < BB) g_flag[e] = 1;          // subgraph center nodes
        if (d < BB) g_flag[src[e]] = 1;     // srcs feeding the subgraph
        return;
    }
    int idx = (b - COUNT_BLOCKS) * 256 + threadIdx.x;
    if (idx >= PREP_ITEMS) return;
    int c    = idx / (64 * 96);
    int rem  = idx % (64 * 96);
    int col  = rem / 96;
    int widx = rem % 96;
    int chunk = widx >> 5;
    int t     = widx & 31;
    int ks    = t >> 3;
    int qq    = (t >> 1) & 3;
    int u     = t & 1;
    int kp    = chunk * 32 + ks * 8 + qq + 4 * u;   // global k-pair index
    int layer = c >> 1;
    bool local = ((c & 1) == 0);
    const float* V = local ? lV : gV;
    const float* W = local ? lW : gW;
    const float* B = local ? lB : gB;

    // stacked K-matrix rows: row<128 -> V[b=row>>6][row&63][col]; else Wself[row-128][col]
    float w[2];
    #pragma unroll
    for (int uu = 0; uu < 2; uu++) {
        int row = 2 * kp + uu;
        if (row < 128) {
            int bb = row >> 6, d = row & 63;
            w[uu] = V[(((size_t)layer * NBASE + bb) * DD + d) * DD + col];
        } else {
            int d = row - 128;
            w[uu] = W[((size_t)layer * DD + d) * DD + col];
        }
    }
    __nv_bfloat162 hi2 = __float22bfloat162_rn(make_float2(w[0], w[1]));
    unsigned uh = *(unsigned*)&hi2;
    float r0 = w[0] - __uint_as_float(uh << 16);
    float r1 = w[1] - __uint_as_float(uh & 0xFFFF0000u);
    __nv_bfloat162 lo2 = __float22bfloat162_rn(make_float2(r0, r1));
    g_WkH[idx] = uh;
    g_WkL[idx] = *(unsigned*)&lo2;
    if (widx == 0) g_Bpack[c * DD + col] = B[layer * DD + col];
}

// ---------------- K2: per-block partial sums of cnt and flag ----------------
__global__ void k2_partial2() {
    __shared__ int s[256];
    int tid = threadIdx.x;
    int i = blockIdx.x * 256 + tid;
    s[tid] = g_cnt[i];
    __syncthreads();
    #pragma unroll
    for (int d = 128; d > 0; d >>= 1) {
        if (tid < d) s[tid] += s[tid + d];
        __syncthreads();
    }
    if (tid == 0) g_blksum[blockIdx.x] = s[0];
    __syncthreads();
    s[tid] = g_flag[i];
    __syncthreads();
    #pragma unroll
    for (int d = 128; d > 0; d >>= 1) {
        if (tid < d) s[tid] += s[tid + d];
        __syncthreads();
    }
    if (tid == 0) g_fsum[blockIdx.x] = s[0];
}

// ---------------- K3: scan both 512-arrays (1 block) ----------------
__global__ void k3_scan2() {
    __shared__ int s[512];
    int tid = threadIdx.x;
    int v = g_blksum[tid];
    s[tid] = v;
    __syncthreads();
    #pragma unroll
    for (int d = 1; d < 512; d <<= 1) {
        int t = (tid >= d) ? s[tid - d] : 0;
        __syncthreads();
        s[tid] += t;
        __syncthreads();
    }
    g_blkpre[tid] = s[tid] - v;
    __syncthreads();
    int f = g_fsum[tid];
    s[tid] = f;
    __syncthreads();
    #pragma unroll
    for (int d = 1; d < 512; d <<= 1) {
        int t = (tid >= d) ? s[tid - d] : 0;
        __syncthreads();
        s[tid] += t;
        __syncthreads();
    }
    g_fpre[tid] = s[tid] - f;
}

// ---------------- K4: write rowptr/cur (+zero cnt), compact frontier (+zero flag) -----
__global__ void k4_write2() {
    __shared__ int s[256];
    int tid = threadIdx.x;
    int i = blockIdx.x * 256 + tid;
    int v = g_cnt[i];
    s[tid] = v;
    __syncthreads();
    #pragma unroll
    for (int d = 1; d < 256; d <<= 1) {
        int t = (tid >= d) ? s[tid - d] : 0;
        __syncthreads();
        s[tid] += t;
        __syncthreads();
    }
    int pos = g_blkpre[blockIdx.x] + s[tid] - v;
    g_rowptr[i] = pos;
    g_cur[i] = pos;
    g_cnt[i] = 0;                       // re-zero for next call
    if (i == NN - 1) g_rowptr[NN] = EE;
    __syncthreads();
    int fv = g_flag[i];
    s[tid] = fv;
    __syncthreads();
    #pragma unroll
    for (int d = 1; d < 256; d <<= 1) {
        int t = (tid >= d) ? s[tid - d] : 0;
        __syncthreads();
        s[tid] += t;
        __syncthreads();
    }
    int fpos = g_fpre[blockIdx.x] + s[tid] - fv;
    if (fv) g_list[fpos] = i;
    g_flag[i] = 0;                      // re-zero for next call
    if (i == NN - 1) g_nfront = fpos + fv;
}

// ---------------- K5: fill CSR payload (packed (se, norm) pairs) ----------------
__global__ void k5_fill(const int* __restrict__ src, const int* __restrict__ dst,
                        const int* __restrict__ etype,
                        const float* __restrict__ mask, const float* __restrict__ mask2) {
    int e = blockIdx.x * blockDim.x + threadIdx.x;
    if (e >= EE) return;
    int d = dst[e];
    int pos = atomicAdd(&g_cur[d], 1);
    float sebits = __int_as_float(src[e] * DD + etype[e]);
    g_ep1[pos] = make_float2(sebits, mask[e]);
    g_ep2[pos] = make_float2(sebits, mask2[e]);
}

// ---------------- basis gather: 16 lanes/node, 4-edge unroll, f32x2 FMA ----------
template <bool IDX>
__global__ __launch_bounds__(256)
void gather2_kernel(const float* __restrict__ h, const float2* __restrict__ ep,
                    const float* __restrict__ C6, int nNodes) {
    int t = blockIdx.x * blockDim.x + threadIdx.x;
    int li = t >> 4;
    int lane = t & 15;
    int limit = IDX ? g_nfront : nNodes;
    if (li >= limit) return;
    int node = IDX ? g_list[li] : li;

    float c00 = __ldg(C6 + 0), c01 = __ldg(C6 + 1);
    float c10 = __ldg(C6 + 2), c11 = __ldg(C6 + 3);
    float c20 = __ldg(C6 + 4), c21 = __ldg(C6 + 5);
    int e0 = g_rowptr[node];
    int e1 = g_rowptr[node + 1];
    // packed accumulators: (dim0,dim1) and (dim2,dim3) per basis
    unsigned long long A00 = 0ULL, A01 = 0ULL, A10 = 0ULL, A11 = 0ULL;
    int e = e0;
    #pragma unroll 1
    for (; e + 4 <= e1; e += 4) {
        float2 ep0 = __ldcs(&ep[e]);
        float2 ep1v = __ldcs(&ep[e + 1]);
        float2 ep2v = __ldcs(&ep[e + 2]);
        float2 ep3v = __ldcs(&ep[e + 3]);
        int p0 = __float_as_int(ep0.x),  p1 = __float_as_int(ep1v.x);
        int p2 = __float_as_int(ep2v.x), p3 = __float_as_int(ep3v.x);
        ulonglong2 h0 = *(const ulonglong2*)(h + (p0 & ~63) + lane * 4);
        ulonglong2 h1 = *(const ulonglong2*)(h + (p1 & ~63) + lane * 4);
        ulonglong2 h2 = *(const ulonglong2*)(h + (p2 & ~63) + lane * 4);
        ulonglong2 h3 = *(const ulonglong2*)(h + (p3 & ~63) + lane * 4);
        int t0 = p0 & 63, t1 = p1 & 63, t2 = p2 & 63, t3 = p3 & 63;
        float wa0 = ep0.y  * (t0 == 0 ? c00 : (t0 == 1 ? c10 : c20));
        float wb0 = ep0.y  * (t0 == 0 ? c01 : (t0 == 1 ? c11 : c21));
        float wa1 = ep1v.y * (t1 == 0 ? c00 : (t1 == 1 ? c10 : c20));
        float wb1 = ep1v.y * (t1 == 0 ? c01 : (t1 == 1 ? c11 : c21));
        float wa2 = ep2v.y * (t2 == 0 ? c00 : (t2 == 1 ? c10 : c20));
        float wb2 = ep2v.y * (t2 == 0 ? c01 : (t2 == 1 ? c11 : c21));
        float wa3 = ep3v.y * (t3 == 0 ? c00 : (t3 == 1 ? c10 : c20));
        float wb3 = ep3v.y * (t3 == 0 ? c01 : (t3 == 1 ? c11 : c21));
        unsigned long long wpa0 = pack2(wa0, wa0), wpb0 = pack2(wb0, wb0);
        unsigned long long wpa1 = pack2(wa1, wa1), wpb1 = pack2(wb1, wb1);
        unsigned long long wpa2 = pack2(wa2, wa2), wpb2 = pack2(wb2, wb2);
        unsigned long long wpa3 = pack2(wa3, wa3), wpb3 = pack2(wb3, wb3);
        FMA2(A00, wpa0, h0.x); FMA2(A01, wpa0, h0.y);
        FMA2(A10, wpb0, h0.x); FMA2(A11, wpb0, h0.y);
        FMA2(A00, wpa1, h1.x); FMA2(A01, wpa1, h1.y);
        FMA2(A10, wpb1, h1.x); FMA2(A11, wpb1, h1.y);
        FMA2(A00, wpa2, h2.x); FMA2(A01, wpa2, h2.y);
        FMA2(A10, wpb2, h2.x); FMA2(A11, wpb2, h2.y);
        FMA2(A00, wpa3, h3.x); FMA2(A01, wpa3, h3.y);
        FMA2(A10, wpb3, h3.x); FMA2(A11, wpb3, h3.y);
    }
    #pragma unroll 1
    for (; e < e1; e++) {
        float2 epv = __ldcs(&ep[e]);
        int p = __float_as_int(epv.x);
        float w = epv.y;
        ulonglong2 hv = *(const ulonglong2*)(h + (p & ~63) + lane * 4);
        int et = p & 63;
        float wa = w * (et == 0 ? c00 : (et == 1 ? c10 : c20));
        float wb = w * (et == 0 ? c01 : (et == 1 ? c11 : c21));
        unsigned long long wpa = pack2(wa, wa), wpb = pack2(wb, wb);
        FMA2(A00, wpa, hv.x); FMA2(A01, wpa, hv.y);
        FMA2(A10, wpb, hv.x); FMA2(A11, wpb, hv.y);
    }
    // unpack + streaming stores (don't let AGGB evict h from L2)
    float4 o0, o1;
    asm("mov.b64 {%0, %1}, %2;" : "=f"(o0.x), "=f"(o0.y) : "l"(A00));
    asm("mov.b64 {%0, %1}, %2;" : "=f"(o0.z), "=f"(o0.w) : "l"(A01));
    asm("mov.b64 {%0, %1}, %2;" : "=f"(o1.x), "=f"(o1.y) : "l"(A10));
    asm("mov.b64 {%0, %1}, %2;" : "=f"(o1.z), "=f"(o1.w) : "l"(A11));
    __stcs((float4*)(g_AGGB + (size_t)li * 128 + lane * 4), o0);
    __stcs((float4*)(g_AGGB + (size_t)li * 128 + 64 + lane * 4), o1);
}

// ---------------- stage-2 GEMM: H = act( [AGGB | h] @ Wk + bias ), bf16 2-way split -----
__device__ __forceinline__ void mma_bf16(float* c, const unsigned* a, const unsigned* b) {
    asm volatile(
        "mma.sync.aligned.m16n8k16.row.col.f32.bf16.bf16.f32 "
        "{%0,%1,%2,%3}, {%4,%5,%6,%7}, {%8,%9}, {%0,%1,%2,%3};"
        : "+f"(c[0]), "+f"(c[1]), "+f"(c[2]), "+f"(c[3])
        : "r"(a[0]), "r"(a[1]), "r"(a[2]), "r"(a[3]), "r"(b[0]), "r"(b[1]));
}

// split float2 into packed bf16x2 hi and lo
__device__ __forceinline__ void split_bf16(float2 v, unsigned& hi, unsigned& lo) {
    __nv_bfloat162 h2 = __float22bfloat162_rn(v);
    hi = *(unsigned*)&h2;
    float r0 = v.x - __uint_as_float(hi << 16);
    float r1 = v.y - __uint_as_float(hi & 0xFFFF0000u);
    __nv_bfloat162 l2 = __float22bfloat162_rn(make_float2(r0, r1));
    lo = *(unsigned*)&l2;
}

#define XS 68
#define WKP 40    // words per column in smem (stride 40 -> conflict-free LDS.64)
#define GEMM_SMEM ((128 * XS + 2 * 64 * WKP) * 4)

template <int ACT, bool IDX>   // ACT: 0 = ELU, 1 = leaky_relu(0.01)
__global__ __launch_bounds__(256, 2)
void gemm2_kernel(const float* __restrict__ h, int conv, float* __restrict__ Hout,
                  int nNodes) {
    extern __shared__ float smem[];
    float*    As  = smem;                           // [128][68]
    unsigned* WsH = (unsigned*)(smem + 128 * XS);   // [64 cols][40 words]
    unsigned* WsL = WsH + 64 * WKP;
    __shared__ int snid[128];

    int limit = IDX ? g_nfront : nNodes;
    int row0 = blockIdx.x * 128;
    if (row0 >= limit) return;

    const unsigned* WpH = g_WkH + (size_t)conv * 64 * 96;
    const unsigned* WpL = g_WkL + (size_t)conv * 64 * 96;
    int tid = threadIdx.x;
    int warp = tid >> 5;
    int lane = tid & 31;
    int group = lane >> 2;
    int q     = lane & 3;

    if (tid < 128) {
        int gr = row0 + tid;
        snid[tid] = IDX ? (gr < limit ? g_list[gr] : 0) : gr;
    }
    __syncthreads();

    float acc[8][4];
    #pragma unroll
    for (int ni = 0; ni < 8; ni++)
        #pragma unroll
        for (int t = 0; t < 4; t++) acc[ni][t] = 0.f;

    #pragma unroll
    for (int chunk = 0; chunk < 3; chunk++) {
        // load X chunk (128x64); AGGB is streaming (read once)
        #pragma unroll
        for (int it = 0; it < 8; it++) {
            int f = tid + it * 256;
            int row = f >> 4, k4 = f & 15;
            float4 v;
            if (chunk < 2)
                v = __ldcs((const float4*)(g_AGGB + (size_t)(row0 + row) * 128 + chunk * 64 + k4 * 4));
            else
                v = *(const float4*)(h + (size_t)snid[row] * DD + k4 * 4);
            *(float4*)(As + row * XS + k4 * 4) = v;
        }
        // load W chunk: 64 cols x 32 words (hi + lo)
        #pragma unroll
        for (int it = 0; it < 2; it++) {
            int f = tid + it * 256;      // 0..511
            int col = f >> 3, w4 = f & 7;
            *(uint4*)(WsH + col * WKP + w4 * 4) =
                *(const uint4*)(WpH + col * 96 + chunk * 32 + w4 * 4);
            *(uint4*)(WsL + col * WKP + w4 * 4) =
                *(const uint4*)(WpL + col * 96 + chunk * 32 + w4 * 4);
        }
        __syncthreads();

        #pragma unroll
        for (int ks = 0; ks < 4; ks++) {
            int k0 = ks * 16;
            int kq = (ks * 4 + q) * 2;
            int rb = warp * 16 + group;
            float2 vA0 = *(const float2*)(As + rb * XS + k0 + 2 * q);
            float2 vA1 = *(const float2*)(As + (rb + 8) * XS + k0 + 2 * q);
            float2 vA2 = *(const float2*)(As + rb * XS + k0 + 2 * q + 8);
            float2 vA3 = *(const float2*)(As + (rb + 8) * XS + k0 + 2 * q + 8);
            unsigned aH[4], aL[4];
            split_bf16(vA0, aH[0], aL[0]);
            split_bf16(vA1, aH[1], aL[1]);
            split_bf16(vA2, aH[2], aL[2]);
            split_bf16(vA3, aH[3], aL[3]);
            #pragma unroll
            for (int ni = 0; ni < 8; ni++) {
                int cn = ni * 8 + group;
                uint2 bh = *(const uint2*)(WsH + cn * WKP + kq);
                uint2 bl = *(const uint2*)(WsL + cn * WKP + kq);
                unsigned bH[2] = { bh.x, bh.y };
                unsigned bL[2] = { bl.x, bl.y };
                mma_bf16(acc[ni], aH, bL);
                mma_bf16(acc[ni], aL, bH);
                mma_bf16(acc[ni], aH, bH);
            }
        }
        __syncthreads();
    }

    // epilogue: +bias, activation, write (scatter via snid when IDX)
    int r0 = row0 + warp * 16 + group;
    bool st0 = !IDX || (r0 < limit);
    bool st8 = !IDX || (r0 + 8 < limit);
    int nid0 = snid[warp * 16 + group];
    int nid8 = snid[warp * 16 + group + 8];
    #pragma unroll
    for (int ni = 0; ni < 8; ni++) {
        int cg = ni * 8 + 2 * q;
        float bv0 = g_Bpack[conv * DD + cg];
        float bv1 = g_Bpack[conv * DD + cg + 1];
        float v0 = acc[ni][0] + bv0, v1 = acc[ni][1] + bv1;
        float v2 = acc[ni][2] + bv0, v3 = acc[ni][3] + bv1;
        if (ACT == 0) {
            v0 = v0 > 0.f ? v0 : expm1f(v0);
            v1 = v1 > 0.f ? v1 : expm1f(v1);
            v2 = v2 > 0.f ? v2 : expm1f(v2);
            v3 = v3 > 0.f ? v3 : expm1f(v3);
        } else {
            v0 = v0 >= 0.f ? v0 : 0.01f * v0;
            v1 = v1 >= 0.f ? v1 : 0.01f * v1;
            v2 = v2 >= 0.f ? v2 : 0.01f * v2;
            v3 = v3 >= 0.f ? v3 : 0.01f * v3;
        }
        if (st0) *(float2*)(Hout + (size_t)nid0 * DD + cg) = make_float2(v0, v1);
        if (st8) *(float2*)(Hout + (size_t)nid8 * DD + cg) = make_float2(v2, v3);
    }
}

// ---------------- MLP head ----------------
__global__ void mlp_kernel(const float* __restrict__ w1, const float* __restrict__ b1,
                           const float* __restrict__ w2, const float* __restrict__ b2,
                           float* __restrict__ out) {
    __shared__ float sub[192];
    __shared__ float red[128];
    int n = blockIdx.x;
    int tid = threadIdx.x;
    if (tid < 64) {
        sub[tid]       = g_Hg0[(size_t)n * DD + tid];
        sub[64 + tid]  = g_Hg1[(size_t)n * DD + tid];
        sub[128 + tid] = g_Hg2[(size_t)n * DD + tid];
    }
    __syncthreads();
    float acc = b1[tid];
    const float* w1r = w1 + tid * 192;
    #pragma unroll 8
    for (int k = 0; k < 192; k++) acc += sub[k] * w1r[k];
    red[tid] = fmaxf(acc, 0.f) * w2[tid];
    __syncthreads();
    #pragma unroll
    for (int s = 64; s > 0; s >>= 1) {
        if (tid < s) red[tid] += red[tid + s];
        __syncthreads();
    }
    if (tid == 0) {
        float z = red[0] + b2[0];
        out[n] = 1.f / (1.f + expf(-z));
    }
}

// ---------------- launch ----------------
extern "C" void kernel_launch(void* const* d_in, const int* in_sizes, int n_in,
                              void* d_out, int out_size) {
    const float* x     = (const float*)d_in[0];
    const int*   src   = (const int*)d_in[1];
    const int*   dst   = (const int*)d_in[2];
    const int*   etype = (const int*)d_in[3];
    const float* mask  = (const float*)d_in[4];
    const float* mask2 = (const float*)d_in[5];
    const float* lV = (const float*)d_in[6];
    const float* lC = (const float*)d_in[7];
    const float* lW = (const float*)d_in[8];
    const float* lB = (const float*)d_in[9];
    const float* gV = (const float*)d_in[10];
    const float* gC = (const float*)d_in[11];
    const float* gW = (const float*)d_in[12];
    const float* gB = (const float*)d_in[13];
    const float* w1 = (const float*)d_in[14];
    const float* b1 = (const float*)d_in[15];
    const float* w2 = (const float*)d_in[16];
    const float* b2 = (const float*)d_in[17];
    float* out = (float*)d_out;

    float *Hl, *Hg0, *Hg1, *Hg2;
    float2 *e1p, *e2p;
    cudaGetSymbolAddress((void**)&Hl,  g_Hl);
    cudaGetSymbolAddress((void**)&Hg0, g_Hg0);
    cudaGetSymbolAddress((void**)&Hg1, g_Hg1);
    cudaGetSymbolAddress((void**)&Hg2, g_Hg2);
    cudaGetSymbolAddress((void**)&e1p, g_ep1);
    cudaGetSymbolAddress((void**)&e2p, g_ep2);

    cudaFuncSetAttribute((const void*)gemm2_kernel<0, false>,
                         cudaFuncAttributeMaxDynamicSharedMemorySize, GEMM_SMEM);
    cudaFuncSetAttribute((const void*)gemm2_kernel<0, true>,
                         cudaFuncAttributeMaxDynamicSharedMemorySize, GEMM_SMEM);
    cudaFuncSetAttribute((const void*)gemm2_kernel<1, false>,
                         cudaFuncAttributeMaxDynamicSharedMemorySize, GEMM_SMEM);

    // prep + CSR + frontier in 5 launches
    k1_combo<<<COUNT_BLOCKS + PREP_BLOCKS, 256>>>(src, dst, lV, lW, lB, gV, gW, gB);
    k2_partial2<<<512, 256>>>();
    k3_scan2<<<1, 512>>>();
    k4_write2<<<512, 256>>>();
    k5_fill<<<EE / 256, 256>>>(src, dst, etype, mask, mask2);

    float* hg[3] = {Hg0, Hg1, Hg2};
    const float* h_in = x;
    for (int layer = 0; layer < LL; layer++) {
        const float* lc = lC + layer * RR * NBASE;
        const float* gc = gC + layer * RR * NBASE;
        if (layer < LL - 1) {
            gather2_kernel<false><<<(NN * 16) / 256, 256>>>(h_in, e1p, lc, NN);
            gemm2_kernel<0, false><<<NN / 128, 256, GEMM_SMEM>>>(h_in, 2 * layer, Hl, NN);
            gather2_kernel<false><<<(NN * 16) / 256, 256>>>(Hl, e2p, gc, NN);
            gemm2_kernel<1, false><<<NN / 128, 256, GEMM_SMEM>>>(Hl, 2 * layer + 1, hg[layer], NN);
        } else {
            // local conv restricted to frontier; global conv over BB subgraph nodes
            gather2_kernel<true><<<(NN * 16) / 256, 256>>>(h_in, e1p, lc, NN);
            gemm2_kernel<0, true><<<NN / 128, 256, GEMM_SMEM>>>(h_in, 2 * layer, Hl, NN);
            gather2_kernel<false><<<(BB * 16) / 256, 256>>>(Hl, e2p, gc, BB);
            gemm2_kernel<1, false><<<BB / 128, 256, GEMM_SMEM>>>(Hl, 2 * layer + 1, hg[layer], BB);
        }
        h_in = hg[layer];
    }

    mlp_kernel<<<BB, 128>>>(w1, b1, w2, b2, out);
}

// round 14
// speedup vs baseline: 1.4818x; 1.4818x over previous
#include <cuda_runtime.h>
#include <cuda_bf16.h>
#include <math.h>

#define NN 131072
#define EE 2097152
#define DD 64
#define LL 3
#define RR 3
#define NBASE 2
#define BB 4096

// ---------------- device scratch (no allocs; zero-initialized at load) ----------------
// W layout: [conv][col][96 words]; word widx: chunk=widx>>5, t=widx&31, ks=t>>3,
// q=(t>>1)&3, u=t&1 -> k-pair = chunk*32 + ks*8 + q + 4u (B-fragment words adjacent)
__device__ unsigned g_WkH[6 * 64 * 96];     // bf16x2 hi pairs
__device__ unsigned g_WkL[6 * 64 * 96];     // bf16x2 lo pairs
__device__ float g_Bpack[6 * DD];
__device__ float g_AGGB[(size_t)NN * 128];  // 2 basis accumulators (compacted rows when IDX)
__device__ float g_Hl[(size_t)NN * DD];
__device__ float g_Hg0[(size_t)NN * DD];
__device__ float g_Hg1[(size_t)NN * DD];
__device__ float g_Hg2[(size_t)NN * DD];
// CSR + frontier structures (graph identical for all 6 convs)
__device__ int    g_cnt[NN];    // zeroed by k4 each call (zero-init on load)
__device__ int    g_flag[NN];   // zeroed by k4 each call
__device__ int    g_cur[NN];
__device__ int    g_rowptr[NN + 1];
__device__ float2 g_ep1[EE];    // (.x = bits(src*64+etype), .y = mask)  in CSR order
__device__ float2 g_ep2[EE];    // (.x = bits(src*64+etype), .y = mask2) in CSR order
__device__ int    g_blksum[512];
__device__ int    g_blkpre[512];
__device__ int    g_fsum[512];
__device__ int    g_fpre[512];
__device__ int    g_list[NN];
__device__ int    g_nfront;

// ---------------- K1: count (CSR histogram) + frontier mark + weight prep (bf16 split) ----
#define COUNT_BLOCKS (EE / 256)          // 8192
#define PREP_ITEMS   (6 * 64 * 96)       // 36864
#define PREP_BLOCKS  ((PREP_ITEMS + 255) / 256)

__global__ void k1_combo(const int* __restrict__ src, const int* __restrict__ dst,
                         const float* __restrict__ lV, const float* __restrict__ lW,
                         const float* __restrict__ lB,
                         const float* __restrict__ gV, const float* __restrict__ gW,
                         const float* __restrict__ gB) {
    int b = blockIdx.x;
    if (b < COUNT_BLOCKS) {
        int e = b * 256 + threadIdx.x;
        int d = dst[e];
        atomicAdd(&g_cnt[d], 1);
        if (e < BB) g_flag[e] = 1;          // subgraph center nodes
        if (d < BB) g_flag[src[e]] = 1;     // srcs feeding the subgraph
        return;
    }
    int idx = (b - COUNT_BLOCKS) * 256 + threadIdx.x;
    if (idx >= PREP_ITEMS) return;
    int c    = idx / (64 * 96);
    int rem  = idx % (64 * 96);
    int col  = rem / 96;
    int widx = rem % 96;
    int chunk = widx >> 5;
    int t     = widx & 31;
    int ks    = t >> 3;
    int qq    = (t >> 1) & 3;
    int u     = t & 1;
    int kp    = chunk * 32 + ks * 8 + qq + 4 * u;   // global k-pair index
    int layer = c >> 1;
    bool local = ((c & 1) == 0);
    const float* V = local ? lV : gV;
    const float* W = local ? lW : gW;
    const float* B = local ? lB : gB;

    // stacked K-matrix rows: row<128 -> V[b=row>>6][row&63][col]; else Wself[row-128][col]
    float w[2];
    #pragma unroll
    for (int uu = 0; uu < 2; uu++) {
        int row = 2 * kp + uu;
        if (row < 128) {
            int bb = row >> 6, d = row & 63;
            w[uu] = V[(((size_t)layer * NBASE + bb) * DD + d) * DD + col];
        } else {
            int d = row - 128;
            w[uu] = W[((size_t)layer * DD + d) * DD + col];
        }
    }
    __nv_bfloat162 hi2 = __float22bfloat162_rn(make_float2(w[0], w[1]));
    unsigned uh = *(unsigned*)&hi2;
    float r0 = w[0] - __uint_as_float(uh << 16);
    float r1 = w[1] - __uint_as_float(uh & 0xFFFF0000u);
    __nv_bfloat162 lo2 = __float22bfloat162_rn(make_float2(r0, r1));
    g_WkH[idx] = uh;
    g_WkL[idx] = *(unsigned*)&lo2;
    if (widx == 0) g_Bpack[c * DD + col] = B[layer * DD + col];
}

// ---------------- K2: per-block partial sums of cnt and flag ----------------
__global__ void k2_partial2() {
    __shared__ int s[256];
    int tid = threadIdx.x;
    int i = blockIdx.x * 256 + tid;
    s[tid] = g_cnt[i];
    __syncthreads();
    #pragma unroll
    for (int d = 128; d > 0; d >>= 1) {
        if (tid < d) s[tid] += s[tid + d];
        __syncthreads();
    }
    if (tid == 0) g_blksum[blockIdx.x] = s[0];
    __syncthreads();
    s[tid] = g_flag[i];
    __syncthreads();
    #pragma unroll
    for (int d = 128; d > 0; d >>= 1) {
        if (tid < d) s[tid] += s[tid + d];
        __syncthreads();
    }
    if (tid == 0) g_fsum[blockIdx.x] = s[0];
}

// ---------------- K3: scan both 512-arrays (1 block) ----------------
__global__ void k3_scan2() {
    __shared__ int s[512];
    int tid = threadIdx.x;
    int v = g_blksum[tid];
    s[tid] = v;
    __syncthreads();
    #pragma unroll
    for (int d = 1; d < 512; d <<= 1) {
        int t = (tid >= d) ? s[tid - d] : 0;
        __syncthreads();
        s[tid] += t;
        __syncthreads();
    }
    g_blkpre[tid] = s[tid] - v;
    __syncthreads();
    int f = g_fsum[tid];
    s[tid] = f;
    __syncthreads();
    #pragma unroll
    for (int d = 1; d < 512; d <<= 1) {
        int t = (tid >= d) ? s[tid - d] : 0;
        __syncthreads();
        s[tid] += t;
        __syncthreads();
    }
    g_fpre[tid] = s[tid] - f;
}

// ---------------- K4: write rowptr/cur (+zero cnt), compact frontier (+zero flag) -----
__global__ void k4_write2() {
    __shared__ int s[256];
    int tid = threadIdx.x;
    int i = blockIdx.x * 256 + tid;
    int v = g_cnt[i];
    s[tid] = v;
    __syncthreads();
    #pragma unroll
    for (int d = 1; d < 256; d <<= 1) {
        int t = (tid >= d) ? s[tid - d] : 0;
        __syncthreads();
        s[tid] += t;
        __syncthreads();
    }
    int pos = g_blkpre[blockIdx.x] + s[tid] - v;
    g_rowptr[i] = pos;
    g_cur[i] = pos;
    g_cnt[i] = 0;                       // re-zero for next call
    if (i == NN - 1) g_rowptr[NN] = EE;
    __syncthreads();
    int fv = g_flag[i];
    s[tid] = fv;
    __syncthreads();
    #pragma unroll
    for (int d = 1; d < 256; d <<= 1) {
        int t = (tid >= d) ? s[tid - d] : 0;
        __syncthreads();
        s[tid] += t;
        __syncthreads();
    }
    int fpos = g_fpre[blockIdx.x] + s[tid] - fv;
    if (fv) g_list[fpos] = i;
    g_flag[i] = 0;                      // re-zero for next call
    if (i == NN - 1) g_nfront = fpos + fv;
}

// ---------------- K5: fill CSR payload (packed (se, norm) pairs) ----------------
__global__ void k5_fill(const int* __restrict__ src, const int* __restrict__ dst,
                        const int* __restrict__ etype,
                        const float* __restrict__ mask, const float* __restrict__ mask2) {
    int e = blockIdx.x * blockDim.x + threadIdx.x;
    if (e >= EE) return;
    int d = dst[e];
    int pos = atomicAdd(&g_cur[d], 1);
    float sebits = __int_as_float(src[e] * DD + etype[e]);
    g_ep1[pos] = make_float2(sebits, mask[e]);
    g_ep2[pos] = make_float2(sebits, mask2[e]);
}

// ---------------- basis gather: 16 lanes/node, 4-edge unroll, streaming hints ----------
template <bool IDX>
__global__ __launch_bounds__(256)
void gather2_kernel(const float* __restrict__ h, const float2* __restrict__ ep,
                    const float* __restrict__ C6, int nNodes) {
    int t = blockIdx.x * blockDim.x + threadIdx.x;
    int li = t >> 4;
    int lane = t & 15;
    int limit = IDX ? g_nfront : nNodes;
    if (li >= limit) return;
    int node = IDX ? g_list[li] : li;

    float c00 = __ldg(C6 + 0), c01 = __ldg(C6 + 1);
    float c10 = __ldg(C6 + 2), c11 = __ldg(C6 + 3);
    float c20 = __ldg(C6 + 4), c21 = __ldg(C6 + 5);
    int e0 = g_rowptr[node];
    int e1 = g_rowptr[node + 1];
    float4 a0 = make_float4(0.f, 0.f, 0.f, 0.f);
    float4 a1 = make_float4(0.f, 0.f, 0.f, 0.f);
    int e = e0;
    #pragma unroll 1
    for (; e + 4 <= e1; e += 4) {
        float2 ep0 = __ldcs(&ep[e]);
        float2 ep1v = __ldcs(&ep[e + 1]);
        float2 ep2v = __ldcs(&ep[e + 2]);
        float2 ep3v = __ldcs(&ep[e + 3]);
        int p0 = __float_as_int(ep0.x),  p1 = __float_as_int(ep1v.x);
        int p2 = __float_as_int(ep2v.x), p3 = __float_as_int(ep3v.x);
        float4 h0 = *(const float4*)(h + (p0 & ~63) + lane * 4);
        float4 h1 = *(const float4*)(h + (p1 & ~63) + lane * 4);
        float4 h2 = *(const float4*)(h + (p2 & ~63) + lane * 4);
        float4 h3 = *(const float4*)(h + (p3 & ~63) + lane * 4);
        int t0 = p0 & 63, t1 = p1 & 63, t2 = p2 & 63, t3 = p3 & 63;
        float wa0 = ep0.y  * (t0 == 0 ? c00 : (t0 == 1 ? c10 : c20));
        float wb0 = ep0.y  * (t0 == 0 ? c01 : (t0 == 1 ? c11 : c21));
        float wa1 = ep1v.y * (t1 == 0 ? c00 : (t1 == 1 ? c10 : c20));
        float wb1 = ep1v.y * (t1 == 0 ? c01 : (t1 == 1 ? c11 : c21));
        float wa2 = ep2v.y * (t2 == 0 ? c00 : (t2 == 1 ? c10 : c20));
        float wb2 = ep2v.y * (t2 == 0 ? c01 : (t2 == 1 ? c11 : c21));
        float wa3 = ep3v.y * (t3 == 0 ? c00 : (t3 == 1 ? c10 : c20));
        float wb3 = ep3v.y * (t3 == 0 ? c01 : (t3 == 1 ? c11 : c21));
        a0.x = fmaf(wa0, h0.x, a0.x); a0.y = fmaf(wa0, h0.y, a0.y);
        a0.z = fmaf(wa0, h0.z, a0.z); a0.w = fmaf(wa0, h0.w, a0.w);
        a1.x = fmaf(wb0, h0.x, a1.x); a1.y = fmaf(wb0, h0.y, a1.y);
        a1.z = fmaf(wb0, h0.z, a1.z); a1.w = fmaf(wb0, h0.w, a1.w);
        a0.x = fmaf(wa1, h1.x, a0.x); a0.y = fmaf(wa1, h1.y, a0.y);
        a0.z = fmaf(wa1, h1.z, a0.z); a0.w = fmaf(wa1, h1.w, a0.w);
        a1.x = fmaf(wb1, h1.x, a1.x); a1.y = fmaf(wb1, h1.y, a1.y);
        a1.z = fmaf(wb1, h1.z, a1.z); a1.w = fmaf(wb1, h1.w, a1.w);
        a0.x = fmaf(wa2, h2.x, a0.x); a0.y = fmaf(wa2, h2.y, a0.y);
        a0.z = fmaf(wa2, h2.z, a0.z); a0.w = fmaf(wa2, h2.w, a0.w);
        a1.x = fmaf(wb2, h2.x, a1.x); a1.y = fmaf(wb2, h2.y, a1.y);
        a1.z = fmaf(wb2, h2.z, a1.z); a1.w = fmaf(wb2, h2.w, a1.w);
        a0.x = fmaf(wa3, h3.x, a0.x); a0.y = fmaf(wa3, h3.y, a0.y);
        a0.z = fmaf(wa3, h3.z, a0.z); a0.w = fmaf(wa3, h3.w, a0.w);
        a1.x = fmaf(wb3, h3.x, a1.x); a1.y = fmaf(wb3, h3.y, a1.y);
        a1.z = fmaf(wb3, h3.z, a1.z); a1.w = fmaf(wb3, h3.w, a1.w);
    }
    #pragma unroll 1
    for (; e < e1; e++) {
        float2 epv = __ldcs(&ep[e]);
        int p = __float_as_int(epv.x);
        float w = epv.y;
        float4 hv = *(const float4*)(h + (p & ~63) + lane * 4);
        int et = p & 63;
        float wa = w * (et == 0 ? c00 : (et == 1 ? c10 : c20));
        float wb = w * (et == 0 ? c01 : (et == 1 ? c11 : c21));
        a0.x = fmaf(wa, hv.x, a0.x); a0.y = fmaf(wa, hv.y, a0.y);
        a0.z = fmaf(wa, hv.z, a0.z); a0.w = fmaf(wa, hv.w, a0.w);
        a1.x = fmaf(wb, hv.x, a1.x); a1.y = fmaf(wb, hv.y, a1.y);
        a1.z = fmaf(wb, hv.z, a1.z); a1.w = fmaf(wb, hv.w, a1.w);
    }
    // streaming stores: don't let AGGB evict h from L2
    __stcs((float4*)(g_AGGB + (size_t)li * 128 + lane * 4), a0);
    __stcs((float4*)(g_AGGB + (size_t)li * 128 + 64 + lane * 4), a1);
}

// ---------------- stage-2 GEMM: H = act( [AGGB | h] @ Wk + bias ), bf16 2-way split -----
__device__ __forceinline__ void mma_bf16(float* c, const unsigned* a, const unsigned* b) {
    asm volatile(
        "mma.sync.aligned.m16n8k16.row.col.f32.bf16.bf16.f32 "
        "{%0,%1,%2,%3}, {%4,%5,%6,%7}, {%8,%9}, {%0,%1,%2,%3};"
        : "+f"(c[0]), "+f"(c[1]), "+f"(c[2]), "+f"(c[3])
        : "r"(a[0]), "r"(a[1]), "r"(a[2]), "r"(a[3]), "r"(b[0]), "r"(b[1]));
}

// split float2 into packed bf16x2 hi and lo
__device__ __forceinline__ void split_bf16(float2 v, unsigned& hi, unsigned& lo) {
    __nv_bfloat162 h2 = __float22bfloat162_rn(v);
    hi = *(unsigned*)&h2;
    float r0 = v.x - __uint_as_float(hi << 16);
    float r1 = v.y - __uint_as_float(hi & 0xFFFF0000u);
    __nv_bfloat162 l2 = __float22bfloat162_rn(make_float2(r0, r1));
    lo = *(unsigned*)&l2;
}

#define XS 68
#define WKP 40    // words per column (stride 40 -> conflict-free 64-bit LDS)
#define GEMM_SMEM ((128 * XS + 2 * 64 * WKP) * 4)

template <int ACT, bool IDX>   // ACT: 0 = ELU, 1 = leaky_relu(0.01)
__global__ __launch_bounds__(256, 2)
void gemm2_kernel(const float* __restrict__ h, int conv, float* __restrict__ Hout,
                  int nNodes) {
    extern __shared__ float smem[];
    float*    As  = smem;                           // [128][68]
    unsigned* WsH = (unsigned*)(smem + 128 * XS);   // [64 cols][40 words]
    unsigned* WsL = WsH + 64 * WKP;
    __shared__ int snid[128];

    int limit = IDX ? g_nfront : nNodes;
    int row0 = blockIdx.x * 128;
    if (row0 >= limit) return;

    const unsigned* WpH = g_WkH + (size_t)conv * 64 * 96;
    const unsigned* WpL = g_WkL + (size_t)conv * 64 * 96;
    int tid = threadIdx.x;
    int warp = tid >> 5;
    int lane = tid & 31;
    int group = lane >> 2;
    int q     = lane & 3;

    if (tid < 128) {
        int gr = row0 + tid;
        snid[tid] = IDX ? (gr < limit ? g_list[gr] : 0) : gr;
    }
    __syncthreads();

    float acc[8][4];
    #pragma unroll
    for (int ni = 0; ni < 8; ni++)
        #pragma unroll
        for (int t = 0; t < 4; t++) acc[ni][t] = 0.f;

    #pragma unroll
    for (int chunk = 0; chunk < 3; chunk++) {
        // load X chunk (128x64); AGGB is streaming (read once)
        #pragma unroll
        for (int it = 0; it < 8; it++) {
            int f = tid + it * 256;
            int row = f >> 4, k4 = f & 15;
            float4 v;
            if (chunk < 2)
                v = __ldcs((const float4*)(g_AGGB + (size_t)(row0 + row) * 128 + chunk * 64 + k4 * 4));
            else
                v = *(const float4*)(h + (size_t)snid[row] * DD + k4 * 4);
            *(float4*)(As + row * XS + k4 * 4) = v;
        }
        // load W chunk: 64 cols x 32 words (hi + lo)
        #pragma unroll
        for (int it = 0; it < 2; it++) {
            int f = tid + it * 256;      // 0..511
            int col = f >> 3, w4 = f & 7;
            *(uint4*)(WsH + col * WKP + w4 * 4) =
                *(const uint4*)(WpH + col * 96 + chunk * 32 + w4 * 4);
            *(uint4*)(WsL + col * WKP + w4 * 4) =
                *(const uint4*)(WpL + col * 96 + chunk * 32 + w4 * 4);
        }
        __syncthreads();

        #pragma unroll
        for (int ks = 0; ks < 4; ks++) {
            int k0 = ks * 16;
            int kq = ks * 8 + q * 2;     // word index of this fragment's adjacent pair
            int rb = warp * 16 + group;
            float2 vA0 = *(const float2*)(As + rb * XS + k0 + 2 * q);
            float2 vA1 = *(const float2*)(As + (rb + 8) * XS + k0 + 2 * q);
            float2 vA2 = *(const float2*)(As + rb * XS + k0 + 2 * q + 8);
            float2 vA3 = *(const float2*)(As + (rb + 8) * XS + k0 + 2 * q + 8);
            unsigned aH[4], aL[4];
            split_bf16(vA0, aH[0], aL[0]);
            split_bf16(vA1, aH[1], aL[1]);
            split_bf16(vA2, aH[2], aL[2]);
            split_bf16(vA3, aH[3], aL[3]);
            #pragma unroll
            for (int ni = 0; ni < 8; ni++) {
                int cn = ni * 8 + group;
                uint2 bh = *(const uint2*)(WsH + cn * WKP + kq);
                uint2 bl = *(const uint2*)(WsL + cn * WKP + kq);
                unsigned bH[2] = { bh.x, bh.y };
                unsigned bL[2] = { bl.x, bl.y };
                mma_bf16(acc[ni], aH, bL);
                mma_bf16(acc[ni], aL, bH);
                mma_bf16(acc[ni], aH, bH);
            }
        }
        __syncthreads();
    }

    // epilogue: +bias, activation, write (scatter via snid when IDX)
    int r0 = row0 + warp * 16 + group;
    bool st0 = !IDX || (r0 < limit);
    bool st8 = !IDX || (r0 + 8 < limit);
    int nid0 = snid[warp * 16 + group];
    int nid8 = snid[warp * 16 + group + 8];
    #pragma unroll
    for (int ni = 0; ni < 8; ni++) {
        int cg = ni * 8 + 2 * q;
        float bv0 = g_Bpack[conv * DD + cg];
        float bv1 = g_Bpack[conv * DD + cg + 1];
        float v0 = acc[ni][0] + bv0, v1 = acc[ni][1] + bv1;
        float v2 = acc[ni][2] + bv0, v3 = acc[ni][3] + bv1;
        if (ACT == 0) {
            v0 = v0 > 0.f ? v0 : expm1f(v0);
            v1 = v1 > 0.f ? v1 : expm1f(v1);
            v2 = v2 > 0.f ? v2 : expm1f(v2);
            v3 = v3 > 0.f ? v3 : expm1f(v3);
        } else {
            v0 = v0 >= 0.f ? v0 : 0.01f * v0;
            v1 = v1 >= 0.f ? v1 : 0.01f * v1;
            v2 = v2 >= 0.f ? v2 : 0.01f * v2;
            v3 = v3 >= 0.f ? v3 : 0.01f * v3;
        }
        if (st0) *(float2*)(Hout + (size_t)nid0 * DD + cg) = make_float2(v0, v1);
        if (st8) *(float2*)(Hout + (size_t)nid8 * DD + cg) = make_float2(v2, v3);
    }
}

// ---------------- MLP head ----------------
__global__ void mlp_kernel(const float* __restrict__ w1, const float* __restrict__ b1,
                           const float* __restrict__ w2, const float* __restrict__ b2,
                           float* __restrict__ out) {
    __shared__ float sub[192];
    __shared__ float red[128];
    int n = blockIdx.x;
    int tid = threadIdx.x;
    if (tid < 64) {
        sub[tid]       = g_Hg0[(size_t)n * DD + tid];
        sub[64 + tid]  = g_Hg1[(size_t)n * DD + tid];
        sub[128 + tid] = g_Hg2[(size_t)n * DD + tid];
    }
    __syncthreads();
    float acc = b1[tid];
    const float* w1r = w1 + tid * 192;
    #pragma unroll 8
    for (int k = 0; k < 192; k++) acc += sub[k] * w1r[k];
    red[tid] = fmaxf(acc, 0.f) * w2[tid];
    __syncthreads();
    #pragma unroll
    for (int s = 64; s > 0; s >>= 1) {
        if (tid < s) red[tid] += red[tid + s];
        __syncthreads();
    }
    if (tid == 0) {
        float z = red[0] + b2[0];
        out[n] = 1.f / (1.f + expf(-z));
    }
}

// ---------------- launch ----------------
extern "C" void kernel_launch(void* const* d_in, const int* in_sizes, int n_in,
                              void* d_out, int out_size) {
    const float* x     = (const float*)d_in[0];
    const int*   src   = (const int*)d_in[1];
    const int*   dst   = (const int*)d_in[2];
    const int*   etype = (const int*)d_in[3];
    const float* mask  = (const float*)d_in[4];
    const float* mask2 = (const float*)d_in[5];
    const float* lV = (const float*)d_in[6];
    const float* lC = (const float*)d_in[7];
    const float* lW = (const float*)d_in[8];
    const float* lB = (const float*)d_in[9];
    const float* gV = (const float*)d_in[10];
    const float* gC = (const float*)d_in[11];
    const float* gW = (const float*)d_in[12];
    const float* gB = (const float*)d_in[13];
    const float* w1 = (const float*)d_in[14];
    const float* b1 = (const float*)d_in[15];
    const float* w2 = (const float*)d_in[16];
    const float* b2 = (const float*)d_in[17];
    float* out = (float*)d_out;

    float *Hl, *Hg0, *Hg1, *Hg2;
    float2 *e1p, *e2p;
    cudaGetSymbolAddress((void**)&Hl,  g_Hl);
    cudaGetSymbolAddress((void**)&Hg0, g_Hg0);
    cudaGetSymbolAddress((void**)&Hg1, g_Hg1);
    cudaGetSymbolAddress((void**)&Hg2, g_Hg2);
    cudaGetSymbolAddress((void**)&e1p, g_ep1);
    cudaGetSymbolAddress((void**)&e2p, g_ep2);

    cudaFuncSetAttribute((const void*)gemm2_kernel<0, false>,
                         cudaFuncAttributeMaxDynamicSharedMemorySize, GEMM_SMEM);
    cudaFuncSetAttribute((const void*)gemm2_kernel<0, true>,
                         cudaFuncAttributeMaxDynamicSharedMemorySize, GEMM_SMEM);
    cudaFuncSetAttribute((const void*)gemm2_kernel<1, false>,
                         cudaFuncAttributeMaxDynamicSharedMemorySize, GEMM_SMEM);

    // prep + CSR + frontier in 5 launches
    k1_combo<<<COUNT_BLOCKS + PREP_BLOCKS, 256>>>(src, dst, lV, lW, lB, gV, gW, gB);
    k2_partial2<<<512, 256>>>();
    k3_scan2<<<1, 512>>>();
    k4_write2<<<512, 256>>>();
    k5_fill<<<EE / 256, 256>>>(src, dst, etype, mask, mask2);

    float* hg[3] = {Hg0, Hg1, Hg2};
    const float* h_in = x;
    for (int layer = 0; layer < LL; layer++) {
        const float* lc = lC + layer * RR * NBASE;
        const float* gc = gC + layer * RR * NBASE;
        if (layer < LL - 1) {
            gather2_kernel<false><<<(NN * 16) / 256, 256>>>(h_in, e1p, lc, NN);
            gemm2_kernel<0, false><<<NN / 128, 256, GEMM_SMEM>>>(h_in, 2 * layer, Hl, NN);
            gather2_kernel<false><<<(NN * 16) / 256, 256>>>(Hl, e2p, gc, NN);
            gemm2_kernel<1, false><<<NN / 128, 256, GEMM_SMEM>>>(Hl, 2 * layer + 1, hg[layer], NN);
        } else {
            // local conv restricted to frontier; global conv over BB subgraph nodes
            gather2_kernel<true><<<(NN * 16) / 256, 256>>>(h_in, e1p, lc, NN);
            gemm2_kernel<0, true><<<NN / 128, 256, GEMM_SMEM>>>(h_in, 2 * layer, Hl, NN);
            gather2_kernel<false><<<(BB * 16) / 256, 256>>>(Hl, e2p, gc, BB);
            gemm2_kernel<1, false><<<BB / 128, 256, GEMM_SMEM>>>(Hl, 2 * layer + 1, hg[layer], BB);
        }
        h_in = hg[layer];
    }

    mlp_kernel<<<BB, 128>>>(w1, b1, w2, b2, out);
}

// round 16
// speedup vs baseline: 1.5281x; 1.0312x over previous
#include <cuda_runtime.h>
#include <cuda_bf16.h>
#include <math.h>

#define NN 131072
#define EE 2097152
#define DD 64
#define LL 3
#define RR 3
#define NBASE 2
#define BB 4096

// ---------------- device scratch (no allocs; zero-initialized at load) ----------------
// W layout: [conv][col][96 words]; word widx: chunk=widx>>5, t=widx&31, ks=t>>3,
// q=(t>>1)&3, u=t&1 -> k-pair = chunk*32 + ks*8 + q + 4u (B-fragment words adjacent)
__device__ unsigned g_WkH[6 * 64 * 96];     // bf16x2 hi pairs
__device__ unsigned g_WkL[6 * 64 * 96];     // bf16x2 lo pairs
__device__ float g_Bpack[6 * DD];
__device__ float g_AGGB[(size_t)NN * 128];  // 2 basis accumulators (compacted rows when IDX)
__device__ float g_Hl[(size_t)NN * DD];
__device__ float g_Hg0[(size_t)NN * DD];
__device__ float g_Hg1[(size_t)NN * DD];
__device__ float g_Hg2[(size_t)NN * DD];
// CSR + frontier structures (graph identical for all 6 convs)
__device__ int    g_cnt[NN];    // zeroed by k4 each call (zero-init on load)
__device__ int    g_flag[NN];   // zeroed by k4 each call
__device__ int    g_cur[NN];
__device__ int    g_rowptr[NN + 1];
__device__ float2 g_ep1[EE];    // (.x = bits(src*64+etype), .y = mask)  in CSR order
__device__ float2 g_ep2[EE];    // (.x = bits(src*64+etype), .y = mask2) in CSR order
__device__ int    g_blksum[512];
__device__ int    g_blkpre[512];
__device__ int    g_fsum[512];
__device__ int    g_fpre[512];
__device__ int    g_list[NN];
__device__ int    g_nfront;

__device__ __forceinline__ unsigned smem_u32(const void* p) {
    unsigned a;
    asm("{ .reg .u64 t; cvta.to.shared.u64 t, %1; cvt.u32.u64 %0, t; }" : "=r"(a) : "l"(p));
    return a;
}
__device__ __forceinline__ void cp16(unsigned saddr, const void* g) {
    asm volatile("cp.async.cg.shared.global [%0], [%1], 16;" :: "r"(saddr), "l"(g) : "memory");
}
#define CP_COMMIT() asm volatile("cp.async.commit_group;" ::: "memory")
#define CP_WAIT(n)  asm volatile("cp.async.wait_group %0;" :: "n"(n) : "memory")

// ---------------- K1: count (CSR histogram) + frontier mark + weight prep (bf16 split) ----
#define COUNT_BLOCKS (EE / 256)          // 8192
#define PREP_ITEMS   (6 * 64 * 96)       // 36864
#define PREP_BLOCKS  ((PREP_ITEMS + 255) / 256)

__global__ void k1_combo(const int* __restrict__ src, const int* __restrict__ dst,
                         const float* __restrict__ lV, const float* __restrict__ lW,
                         const float* __restrict__ lB,
                         const float* __restrict__ gV, const float* __restrict__ gW,
                         const float* __restrict__ gB) {
    int b = blockIdx.x;
    if (b < COUNT_BLOCKS) {
        int e = b * 256 + threadIdx.x;
        int d = dst[e];
        atomicAdd(&g_cnt[d], 1);
        if (e < BB) g_flag[e] = 1;          // subgraph center nodes
        if (d < BB) g_flag[src[e]] = 1;     // srcs feeding the subgraph
        return;
    }
    int idx = (b - COUNT_BLOCKS) * 256 + threadIdx.x;
    if (idx >= PREP_ITEMS) return;
    int c    = idx / (64 * 96);
    int rem  = idx % (64 * 96);
    int col  = rem / 96;
    int widx = rem % 96;
    int chunk = widx >> 5;
    int t     = widx & 31;
    int ks    = t >> 3;
    int qq    = (t >> 1) & 3;
    int u     = t & 1;
    int kp    = chunk * 32 + ks * 8 + qq + 4 * u;   // global k-pair index
    int layer = c >> 1;
    bool local = ((c & 1) == 0);
    const float* V = local ? lV : gV;
    const float* W = local ? lW : gW;
    const float* B = local ? lB : gB;

    // stacked K-matrix rows: row<128 -> V[b=row>>6][row&63][col]; else Wself[row-128][col]
    float w[2];
    #pragma unroll
    for (int uu = 0; uu < 2; uu++) {
        int row = 2 * kp + uu;
        if (row < 128) {
            int bb = row >> 6, d = row & 63;
            w[uu] = V[(((size_t)layer * NBASE + bb) * DD + d) * DD + col];
        } else {
            int d = row - 128;
            w[uu] = W[((size_t)layer * DD + d) * DD + col];
        }
    }
    __nv_bfloat162 hi2 = __float22bfloat162_rn(make_float2(w[0], w[1]));
    unsigned uh = *(unsigned*)&hi2;
    float r0 = w[0] - __uint_as_float(uh << 16);
    float r1 = w[1] - __uint_as_float(uh & 0xFFFF0000u);
    __nv_bfloat162 lo2 = __float22bfloat162_rn(make_float2(r0, r1));
    g_WkH[idx] = uh;
    g_WkL[idx] = *(unsigned*)&lo2;
    if (widx == 0) g_Bpack[c * DD + col] = B[layer * DD + col];
}

// ---------------- K2: per-block partial sums of cnt and flag ----------------
__global__ void k2_partial2() {
    __shared__ int s[256];
    int tid = threadIdx.x;
    int i = blockIdx.x * 256 + tid;
    s[tid] = g_cnt[i];
    __syncthreads();
    #pragma unroll
    for (int d = 128; d > 0; d >>= 1) {
        if (tid < d) s[tid] += s[tid + d];
        __syncthreads();
    }
    if (tid == 0) g_blksum[blockIdx.x] = s[0];
    __syncthreads();
    s[tid] = g_flag[i];
    __syncthreads();
    #pragma unroll
    for (int d = 128; d > 0; d >>= 1) {
        if (tid < d) s[tid] += s[tid + d];
        __syncthreads();
    }
    if (tid == 0) g_fsum[blockIdx.x] = s[0];
}

// ---------------- K3: scan both 512-arrays (1 block) ----------------
__global__ void k3_scan2() {
    __shared__ int s[512];
    int tid = threadIdx.x;
    int v = g_blksum[tid];
    s[tid] = v;
    __syncthreads();
    #pragma unroll
    for (int d = 1; d < 512; d <<= 1) {
        int t = (tid >= d) ? s[tid - d] : 0;
        __syncthreads();
        s[tid] += t;
        __syncthreads();
    }
    g_blkpre[tid] = s[tid] - v;
    __syncthreads();
    int f = g_fsum[tid];
    s[tid] = f;
    __syncthreads();
    #pragma unroll
    for (int d = 1; d < 512; d <<= 1) {
        int t = (tid >= d) ? s[tid - d] : 0;
        __syncthreads();
        s[tid] += t;
        __syncthreads();
    }
    g_fpre[tid] = s[tid] - f;
}

// ---------------- K4: write rowptr/cur (+zero cnt), compact frontier (+zero flag) -----
__global__ void k4_write2() {
    __shared__ int s[256];
    int tid = threadIdx.x;
    int i = blockIdx.x * 256 + tid;
    int v = g_cnt[i];
    s[tid] = v;
    __syncthreads();
    #pragma unroll
    for (int d = 1; d < 256; d <<= 1) {
        int t = (tid >= d) ? s[tid - d] : 0;
        __syncthreads();
        s[tid] += t;
        __syncthreads();
    }
    int pos = g_blkpre[blockIdx.x] + s[tid] - v;
    g_rowptr[i] = pos;
    g_cur[i] = pos;
    g_cnt[i] = 0;
    if (i == NN - 1) g_rowptr[NN] = EE;
    __syncthreads();
    int fv = g_flag[i];
    s[tid] = fv;
    __syncthreads();
    #pragma unroll
    for (int d = 1; d < 256; d <<= 1) {
        int t = (tid >= d) ? s[tid - d] : 0;
        __syncthreads();
        s[tid] += t;
        __syncthreads();
    }
    int fpos = g_fpre[blockIdx.x] + s[tid] - fv;
    if (fv) g_list[fpos] = i;
    g_flag[i] = 0;
    if (i == NN - 1) g_nfront = fpos + fv;
}

// ---------------- K5: fill CSR payload (packed (se, norm) pairs) ----------------
__global__ void k5_fill(const int* __restrict__ src, const int* __restrict__ dst,
                        const int* __restrict__ etype,
                        const float* __restrict__ mask, const float* __restrict__ mask2) {
    int e = blockIdx.x * blockDim.x + threadIdx.x;
    if (e >= EE) return;
    int d = dst[e];
    int pos = atomicAdd(&g_cur[d], 1);
    float sebits = __int_as_float(src[e] * DD + etype[e]);
    g_ep1[pos] = make_float2(sebits, mask[e]);
    g_ep2[pos] = make_float2(sebits, mask2[e]);
}

// ---------------- basis gather: 16 lanes/node, 4-edge unroll, streaming hints ----------
template <bool IDX>
__global__ __launch_bounds__(256)
void gather2_kernel(const float* __restrict__ h, const float2* __restrict__ ep,
                    const float* __restrict__ C6, int nNodes) {
    int t = blockIdx.x * blockDim.x + threadIdx.x;
    int li = t >> 4;
    int lane = t & 15;
    int limit = IDX ? g_nfront : nNodes;
    if (li >= limit) return;
    int node = IDX ? g_list[li] : li;

    float c00 = __ldg(C6 + 0), c01 = __ldg(C6 + 1);
    float c10 = __ldg(C6 + 2), c11 = __ldg(C6 + 3);
    float c20 = __ldg(C6 + 4), c21 = __ldg(C6 + 5);
    int e0 = g_rowptr[node];
    int e1 = g_rowptr[node + 1];
    float4 a0 = make_float4(0.f, 0.f, 0.f, 0.f);
    float4 a1 = make_float4(0.f, 0.f, 0.f, 0.f);
    int e = e0;
    #pragma unroll 1
    for (; e + 4 <= e1; e += 4) {
        float2 ep0 = __ldcs(&ep[e]);
        float2 ep1v = __ldcs(&ep[e + 1]);
        float2 ep2v = __ldcs(&ep[e + 2]);
        float2 ep3v = __ldcs(&ep[e + 3]);
        int p0 = __float_as_int(ep0.x),  p1 = __float_as_int(ep1v.x);
        int p2 = __float_as_int(ep2v.x), p3 = __float_as_int(ep3v.x);
        float4 h0 = *(const float4*)(h + (p0 & ~63) + lane * 4);
        float4 h1 = *(const float4*)(h + (p1 & ~63) + lane * 4);
        float4 h2 = *(const float4*)(h + (p2 & ~63) + lane * 4);
        float4 h3 = *(const float4*)(h + (p3 & ~63) + lane * 4);
        int t0 = p0 & 63, t1 = p1 & 63, t2 = p2 & 63, t3 = p3 & 63;
        float wa0 = ep0.y  * (t0 == 0 ? c00 : (t0 == 1 ? c10 : c20));
        float wb0 = ep0.y  * (t0 == 0 ? c01 : (t0 == 1 ? c11 : c21));
        float wa1 = ep1v.y * (t1 == 0 ? c00 : (t1 == 1 ? c10 : c20));
        float wb1 = ep1v.y * (t1 == 0 ? c01 : (t1 == 1 ? c11 : c21));
        float wa2 = ep2v.y * (t2 == 0 ? c00 : (t2 == 1 ? c10 : c20));
        float wb2 = ep2v.y * (t2 == 0 ? c01 : (t2 == 1 ? c11 : c21));
        float wa3 = ep3v.y * (t3 == 0 ? c00 : (t3 == 1 ? c10 : c20));
        float wb3 = ep3v.y * (t3 == 0 ? c01 : (t3 == 1 ? c11 : c21));
        a0.x = fmaf(wa0, h0.x, a0.x); a0.y = fmaf(wa0, h0.y, a0.y);
        a0.z = fmaf(wa0, h0.z, a0.z); a0.w = fmaf(wa0, h0.w, a0.w);
        a1.x = fmaf(wb0, h0.x, a1.x); a1.y = fmaf(wb0, h0.y, a1.y);
        a1.z = fmaf(wb0, h0.z, a1.z); a1.w = fmaf(wb0, h0.w, a1.w);
        a0.x = fmaf(wa1, h1.x, a0.x); a0.y = fmaf(wa1, h1.y, a0.y);
        a0.z = fmaf(wa1, h1.z, a0.z); a0.w = fmaf(wa1, h1.w, a0.w);
        a1.x = fmaf(wb1, h1.x, a1.x); a1.y = fmaf(wb1, h1.y, a1.y);
        a1.z = fmaf(wb1, h1.z, a1.z); a1.w = fmaf(wb1, h1.w, a1.w);
        a0.x = fmaf(wa2, h2.x, a0.x); a0.y = fmaf(wa2, h2.y, a0.y);
        a0.z = fmaf(wa2, h2.z, a0.z); a0.w = fmaf(wa2, h2.w, a0.w);
        a1.x = fmaf(wb2, h2.x, a1.x); a1.y = fmaf(wb2, h2.y, a1.y);
        a1.z = fmaf(wb2, h2.z, a1.z); a1.w = fmaf(wb2, h2.w, a1.w);
        a0.x = fmaf(wa3, h3.x, a0.x); a0.y = fmaf(wa3, h3.y, a0.y);
        a0.z = fmaf(wa3, h3.z, a0.z); a0.w = fmaf(wa3, h3.w, a0.w);
        a1.x = fmaf(wb3, h3.x, a1.x); a1.y = fmaf(wb3, h3.y, a1.y);
        a1.z = fmaf(wb3, h3.z, a1.z); a1.w = fmaf(wb3, h3.w, a1.w);
    }
    #pragma unroll 1
    for (; e < e1; e++) {
        float2 epv = __ldcs(&ep[e]);
        int p = __float_as_int(epv.x);
        float w = epv.y;
        float4 hv = *(const float4*)(h + (p & ~63) + lane * 4);
        int et = p & 63;
        float wa = w * (et == 0 ? c00 : (et == 1 ? c10 : c20));
        float wb = w * (et == 0 ? c01 : (et == 1 ? c11 : c21));
        a0.x = fmaf(wa, hv.x, a0.x); a0.y = fmaf(wa, hv.y, a0.y);
        a0.z = fmaf(wa, hv.z, a0.z); a0.w = fmaf(wa, hv.w, a0.w);
        a1.x = fmaf(wb, hv.x, a1.x); a1.y = fmaf(wb, hv.y, a1.y);
        a1.z = fmaf(wb, hv.z, a1.z); a1.w = fmaf(wb, hv.w, a1.w);
    }
    __stcs((float4*)(g_AGGB + (size_t)li * 128 + lane * 4), a0);
    __stcs((float4*)(g_AGGB + (size_t)li * 128 + 64 + lane * 4), a1);
}

// ---------------- stage-2 GEMM: bf16 2-way split mma.sync + cp.async double buffer -----
__device__ __forceinline__ void mma_bf16(float* c, const unsigned* a, const unsigned* b) {
    asm volatile(
        "mma.sync.aligned.m16n8k16.row.col.f32.bf16.bf16.f32 "
        "{%0,%1,%2,%3}, {%4,%5,%6,%7}, {%8,%9}, {%0,%1,%2,%3};"
        : "+f"(c[0]), "+f"(c[1]), "+f"(c[2]), "+f"(c[3])
        : "r"(a[0]), "r"(a[1]), "r"(a[2]), "r"(a[3]), "r"(b[0]), "r"(b[1]));
}

__device__ __forceinline__ void split_bf16(float2 v, unsigned& hi, unsigned& lo) {
    __nv_bfloat162 h2 = __float22bfloat162_rn(v);
    hi = *(unsigned*)&h2;
    float r0 = v.x - __uint_as_float(hi << 16);
    float r1 = v.y - __uint_as_float(hi & 0xFFFF0000u);
    __nv_bfloat162 l2 = __float22bfloat162_rn(make_float2(r0, r1));
    lo = *(unsigned*)&l2;
}

#define XS 68
#define WKP 40
// double buffers: As[2] (128*68 floats each) then WsH0, WsL0, WsH1, WsL1 (64*40 words each)
#define OFF_AS(b)  ((b) * 128 * XS)
#define OFF_WH(b)  (2 * 128 * XS + (b) * 2 * 64 * WKP)
#define OFF_WL(b)  (OFF_WH(b) + 64 * WKP)
#define GEMM_SMEM ((2 * 128 * XS + 4 * 64 * WKP) * 4)

template <int ACT, bool IDX>   // ACT: 0 = ELU, 1 = leaky_relu(0.01)
__global__ __launch_bounds__(256, 2)
void gemm2_kernel(const float* __restrict__ h, int conv, float* __restrict__ Hout,
                  int nNodes) {
    extern __shared__ float smem[];
    __shared__ int snid[128];

    int limit = IDX ? g_nfront : nNodes;
    int row0 = blockIdx.x * 128;
    if (row0 >= limit) return;

    const unsigned* WpH = g_WkH + (size_t)conv * 64 * 96;
    const unsigned* WpL = g_WkL + (size_t)conv * 64 * 96;
    int tid = threadIdx.x;
    int warp = tid >> 5;
    int lane = tid & 31;
    int group = lane >> 2;
    int q     = lane & 3;
    unsigned sbase = smem_u32(smem);

    // per-thread load coordinates
    int xrow = tid >> 4, xk4 = tid & 15;          // X: 2 iterations add +16 rows... (8 total below)
    int wcol = tid >> 3, ww4 = tid & 7;           // W: 2 cols halves

    if (tid < 128) {
        int gr = row0 + tid;
        snid[tid] = IDX ? (gr < limit ? g_list[gr] : 0) : gr;
    }

    // ---- async load issue helper (chunk -> buffer buf) ----
    auto issue_chunk = [&](int chunk, int buf) {
        unsigned asb = sbase + OFF_AS(buf) * 4;
        #pragma unroll
        for (int it = 0; it < 8; it++) {
            int f = tid + it * 256;
            int row = f >> 4, k4 = f & 15;
            const float* g;
            if (chunk < 2)
                g = g_AGGB + (size_t)(row0 + row) * 128 + chunk * 64 + k4 * 4;
            else
                g = h + (size_t)snid[row] * DD + k4 * 4;
            cp16(asb + (unsigned)(row * XS + k4 * 4) * 4, g);
        }
        unsigned whb = sbase + OFF_WH(buf) * 4;
        unsigned wlb = sbase + OFF_WL(buf) * 4;
        #pragma unroll
        for (int it = 0; it < 2; it++) {
            int f = tid + it * 256;
            int col = f >> 3, w4 = f & 7;
            cp16(whb + (unsigned)(col * WKP + w4 * 4) * 4, WpH + col * 96 + chunk * 32 + w4 * 4);
            cp16(wlb + (unsigned)(col * WKP + w4 * 4) * 4, WpL + col * 96 + chunk * 32 + w4 * 4);
        }
        CP_COMMIT();
    };

    float acc[8][4];
    #pragma unroll
    for (int ni = 0; ni < 8; ni++)
        #pragma unroll
        for (int t = 0; t < 4; t++) acc[ni][t] = 0.f;

    // prologue: chunk0 (no snid needed), sync for snid, chunk1
    issue_chunk(0, 0);
    __syncthreads();            // snid visible to all
    issue_chunk(1, 1);

    #pragma unroll
    for (int chunk = 0; chunk < 3; chunk++) {
        int buf = chunk == 2 ? 0 : chunk;   // 0,1,0
        if (chunk < 2) { CP_WAIT(1); } else { CP_WAIT(0); }
        __syncthreads();        // make async-filled smem visible to all threads

        const float*    As  = smem + OFF_AS(buf);
        const unsigned* WsH = (const unsigned*)(smem + OFF_WH(buf));
        const unsigned* WsL = (const unsigned*)(smem + OFF_WL(buf));

        #pragma unroll
        for (int ks = 0; ks < 4; ks++) {
            int k0 = ks * 16;
            int kq = ks * 8 + q * 2;
            int rb = warp * 16 + group;
            float2 vA0 = *(const float2*)(As + rb * XS + k0 + 2 * q);
            float2 vA1 = *(const float2*)(As + (rb + 8) * XS + k0 + 2 * q);
            float2 vA2 = *(const float2*)(As + rb * XS + k0 + 2 * q + 8);
            float2 vA3 = *(const float2*)(As + (rb + 8) * XS + k0 + 2 * q + 8);
            unsigned aH[4], aL[4];
            split_bf16(vA0, aH[0], aL[0]);
            split_bf16(vA1, aH[1], aL[1]);
            split_bf16(vA2, aH[2], aL[2]);
            split_bf16(vA3, aH[3], aL[3]);
            #pragma unroll
            for (int ni = 0; ni < 8; ni++) {
                int cn = ni * 8 + group;
                uint2 bh = *(const uint2*)(WsH + cn * WKP + kq);
                uint2 bl = *(const uint2*)(WsL + cn * WKP + kq);
                unsigned bH[2] = { bh.x, bh.y };
                unsigned bL[2] = { bl.x, bl.y };
                mma_bf16(acc[ni], aH, bL);
                mma_bf16(acc[ni], aL, bH);
                mma_bf16(acc[ni], aH, bH);
            }
        }
        __syncthreads();        // buffer free before reuse
        if (chunk == 0) issue_chunk(2, 0);
    }

    // epilogue: +bias, activation, write (scatter via snid when IDX)
    int r0 = row0 + warp * 16 + group;
    bool st0 = !IDX || (r0 < limit);
    bool st8 = !IDX || (r0 + 8 < limit);
    int nid0 = snid[warp * 16 + group];
    int nid8 = snid[warp * 16 + group + 8];
    #pragma unroll
    for (int ni = 0; ni < 8; ni++) {
        int cg = ni * 8 + 2 * q;
        float bv0 = g_Bpack[conv * DD + cg];
        float bv1 = g_Bpack[conv * DD + cg + 1];
        float v0 = acc[ni][0] + bv0, v1 = acc[ni][1] + bv1;
        float v2 = acc[ni][2] + bv0, v3 = acc[ni][3] + bv1;
        if (ACT == 0) {
            v0 = v0 > 0.f ? v0 : expm1f(v0);
            v1 = v1 > 0.f ? v1 : expm1f(v1);
            v2 = v2 > 0.f ? v2 : expm1f(v2);
            v3 = v3 > 0.f ? v3 : expm1f(v3);
        } else {
            v0 = v0 >= 0.f ? v0 : 0.01f * v0;
            v1 = v1 >= 0.f ? v1 : 0.01f * v1;
            v2 = v2 >= 0.f ? v2 : 0.01f * v2;
            v3 = v3 >= 0.f ? v3 : 0.01f * v3;
        }
        if (st0) *(float2*)(Hout + (size_t)nid0 * DD + cg) = make_float2(v0, v1);
        if (st8) *(float2*)(Hout + (size_t)nid8 * DD + cg) = make_float2(v2, v3);
    }
}

// ---------------- MLP head ----------------
__global__ void mlp_kernel(const float* __restrict__ w1, const float* __restrict__ b1,
                           const float* __restrict__ w2, const float* __restrict__ b2,
                           float* __restrict__ out) {
    __shared__ float sub[192];
    __shared__ float red[128];
    int n = blockIdx.x;
    int tid = threadIdx.x;
    if (tid < 64) {
        sub[tid]       = g_Hg0[(size_t)n * DD + tid];
        sub[64 + tid]  = g_Hg1[(size_t)n * DD + tid];
        sub[128 + tid] = g_Hg2[(size_t)n * DD + tid];
    }
    __syncthreads();
    float acc = b1[tid];
    const float* w1r = w1 + tid * 192;
    #pragma unroll 8
    for (int k = 0; k < 192; k++) acc += sub[k] * w1r[k];
    red[tid] = fmaxf(acc, 0.f) * w2[tid];
    __syncthreads();
    #pragma unroll
    for (int s = 64; s > 0; s >>= 1) {
        if (tid < s) red[tid] += red[tid + s];
        __syncthreads();
    }
    if (tid == 0) {
        float z = red[0] + b2[0];
        out[n] = 1.f / (1.f + expf(-z));
    }
}

// ---------------- launch ----------------
extern "C" void kernel_launch(void* const* d_in, const int* in_sizes, int n_in,
                              void* d_out, int out_size) {
    const float* x     = (const float*)d_in[0];
    const int*   src   = (const int*)d_in[1];
    const int*   dst   = (const int*)d_in[2];
    const int*   etype = (const int*)d_in[3];
    const float* mask  = (const float*)d_in[4];
    const float* mask2 = (const float*)d_in[5];
    const float* lV = (const float*)d_in[6];
    const float* lC = (const float*)d_in[7];
    const float* lW = (const float*)d_in[8];
    const float* lB = (const float*)d_in[9];
    const float* gV = (const float*)d_in[10];
    const float* gC = (const float*)d_in[11];
    const float* gW = (const float*)d_in[12];
    const float* gB = (const float*)d_in[13];
    const float* w1 = (const float*)d_in[14];
    const float* b1 = (const float*)d_in[15];
    const float* w2 = (const float*)d_in[16];
    const float* b2 = (const float*)d_in[17];
    float* out = (float*)d_out;

    float *Hl, *Hg0, *Hg1, *Hg2;
    float2 *e1p, *e2p;
    cudaGetSymbolAddress((void**)&Hl,  g_Hl);
    cudaGetSymbolAddress((void**)&Hg0, g_Hg0);
    cudaGetSymbolAddress((void**)&Hg1, g_Hg1);
    cudaGetSymbolAddress((void**)&Hg2, g_Hg2);
    cudaGetSymbolAddress((void**)&e1p, g_ep1);
    cudaGetSymbolAddress((void**)&e2p, g_ep2);

    cudaFuncSetAttribute((const void*)gemm2_kernel<0, false>,
                         cudaFuncAttributeMaxDynamicSharedMemorySize, GEMM_SMEM);
    cudaFuncSetAttribute((const void*)gemm2_kernel<0, true>,
                         cudaFuncAttributeMaxDynamicSharedMemorySize, GEMM_SMEM);
    cudaFuncSetAttribute((const void*)gemm2_kernel<1, false>,
                         cudaFuncAttributeMaxDynamicSharedMemorySize, GEMM_SMEM);

    // prep + CSR + frontier in 5 launches
    k1_combo<<<COUNT_BLOCKS + PREP_BLOCKS, 256>>>(src, dst, lV, lW, lB, gV, gW, gB);
    k2_partial2<<<512, 256>>>();
    k3_scan2<<<1, 512>>>();
    k4_write2<<<512, 256>>>();
    k5_fill<<<EE / 256, 256>>>(src, dst, etype, mask, mask2);

    float* hg[3] = {Hg0, Hg1, Hg2};
    const float* h_in = x;
    for (int layer = 0; layer < LL; layer++) {
        const float* lc = lC + layer * RR * NBASE;
        const float* gc = gC + layer * RR * NBASE;
        if (layer < LL - 1) {
            gather2_kernel<false><<<(NN * 16) / 256, 256>>>(h_in, e1p, lc, NN);
            gemm2_kernel<0, false><<<NN / 128, 256, GEMM_SMEM>>>(h_in, 2 * layer, Hl, NN);
            gather2_kernel<false><<<(NN * 16) / 256, 256>>>(Hl, e2p, gc, NN);
            gemm2_kernel<1, false><<<NN / 128, 256, GEMM_SMEM>>>(Hl, 2 * layer + 1, hg[layer], NN);
        } else {
            gather2_kernel<true><<<(NN * 16) / 256, 256>>>(h_in, e1p, lc, NN);
            gemm2_kernel<0, true><<<NN / 128, 256, GEMM_SMEM>>>(h_in, 2 * layer, Hl, NN);
            gather2_kernel<false><<<(BB * 16) / 256, 256>>>(Hl, e2p, gc, BB);
            gemm2_kernel<1, false><<<BB / 128, 256, GEMM_SMEM>>>(Hl, 2 * layer + 1, hg[layer], BB);
        }
        h_in = hg[layer];
    }

    mlp_kernel<<<BB, 128>>>(w1, b1, w2, b2, out);
}